// round 6
// baseline (speedup 1.0000x reference)
#include <cuda_runtime.h>
#include <math.h>

#define BSZ  32
#define SEQ  4096
#define ENC  512
#define TMAX 64

// Scratch: per-(b,t) logit-difference contributions. __device__ globals (no alloc).
__device__ float g_dl[BSZ * TMAX];
__device__ float g_dr[BSZ * TMAX];

// Kernel 1: gather + two weight-difference dot products per (b,t).
// 256 blocks x 256 threads; each warp owns one (b,t) row (2048 rows total).
__global__ void __launch_bounds__(256) proj_kernel(const float* __restrict__ enc,
                                                   const int*   __restrict__ ids,
                                                   const float* __restrict__ W) {
    __shared__ float wdl[ENC];
    __shared__ float wdr[ENC];
    const int tid = threadIdx.x;

    // Stage weight-difference vectors once per block.
    // W layout (2, 2*ENC) row-major: W0 = W[0..1024), W1 = W[1024..2048).
    for (int i = tid; i < ENC; i += 256) {
        wdl[i] = W[1024 + i]       - W[i];          // Wl1 - Wl0
        wdr[i] = W[1536 + i]       - W[512 + i];    // Wr1 - Wr0
    }
    __syncthreads();

    const int warp = tid >> 5;
    const int lane = tid & 31;
    const int row  = blockIdx.x * 8 + warp;         // 0..2047  == b*64 + t
    const int b    = row >> 6;
    const int id   = ids[row];

    const float4* __restrict__ src = (const float4*)(enc + ((size_t)b * SEQ + id) * ENC);
    const float4* __restrict__ l4  = (const float4*)wdl;
    const float4* __restrict__ r4  = (const float4*)wdr;

    float dl = 0.f, dr = 0.f;
#pragma unroll
    for (int i = 0; i < 4; i++) {
        const int c = lane + i * 32;                // 128 float4 per row
        const float4 x  = src[c];
        const float4 a  = l4[c];
        const float4 bb = r4[c];
        dl = fmaf(x.x, a.x,  fmaf(x.y, a.y,  fmaf(x.z, a.z,  fmaf(x.w, a.w,  dl))));
        dr = fmaf(x.x, bb.x, fmaf(x.y, bb.y, fmaf(x.z, bb.z, fmaf(x.w, bb.w, dr))));
    }
#pragma unroll
    for (int o = 16; o; o >>= 1) {
        dl += __shfl_xor_sync(0xffffffffu, dl, o);
        dr += __shfl_xor_sync(0xffffffffu, dr, o);
    }
    if (lane == 0) {
        g_dl[row] = dl;
        g_dr[row] = dr;
    }
}

// Kernel 2: pairwise masked CE + reduction. Single CTA (work is tiny).
__global__ void __launch_bounds__(1024) loss_kernel(const int*   __restrict__ tl,
                                                    const float* __restrict__ bias,
                                                    float*       __restrict__ out) {
    __shared__ float sdl[BSZ * TMAX];
    __shared__ float sdr[BSZ * TMAX];
    __shared__ int   slen[BSZ];
    __shared__ float swsum[32];
    __shared__ int   swcnt[32];

    const int tid = threadIdx.x;
    for (int i = tid; i < BSZ * TMAX; i += 1024) {
        sdl[i] = g_dl[i];
        sdr[i] = g_dr[i];
    }
    if (tid < BSZ) slen[tid] = tl[tid];
    __syncthreads();

    const float db = bias[1] - bias[0];

    float sum = 0.f;
    int   cnt = 0;
    // 32*64*64 = 131072 pairs, 128 per thread.
    for (int p = tid; p < BSZ * TMAX * TMAX; p += 1024) {
        const int b = p >> 12;
        const int j = (p >> 6) & 63;
        const int k = p & 63;
        if (k < j && j < slen[b]) {
            const float d = sdl[b * 64 + j] + sdr[b * 64 + k] + db;
            const float x = (k == j - 1) ? -d : d;       // label -> -logp1, else -logp0
            // numerically stable softplus(x) = max(x,0) + log1p(exp(-|x|))
            const float ce = fmaxf(x, 0.f) + log1pf(expf(-fabsf(x)));
            sum += ce;
            cnt += 1;
        }
    }

#pragma unroll
    for (int o = 16; o; o >>= 1) {
        sum += __shfl_xor_sync(0xffffffffu, sum, o);
        cnt += __shfl_xor_sync(0xffffffffu, cnt, o);
    }
    const int warp = tid >> 5;
    const int lane = tid & 31;
    if (lane == 0) { swsum[warp] = sum; swcnt[warp] = cnt; }
    __syncthreads();
    if (warp == 0) {
        sum = (lane < 32) ? swsum[lane] : 0.f;
        cnt = (lane < 32) ? swcnt[lane] : 0;
#pragma unroll
        for (int o = 16; o; o >>= 1) {
            sum += __shfl_xor_sync(0xffffffffu, sum, o);
            cnt += __shfl_xor_sync(0xffffffffu, cnt, o);
        }
        if (lane == 0) out[0] = sum / (float)max(cnt, 1);
    }
}

extern "C" void kernel_launch(void* const* d_in, const int* in_sizes, int n_in,
                              void* d_out, int out_size) {
    // metadata order: encoder_output, his_turn_end_ids, turn_lengths, W, b
    const float* enc  = (const float*)d_in[0];
    const int*   ids  = (const int*)  d_in[1];
    const int*   tl   = (const int*)  d_in[2];
    const float* W    = (const float*)d_in[3];
    const float* bias = (const float*)d_in[4];
    float*       out  = (float*)d_out;

    proj_kernel<<<256, 256>>>(enc, ids, W);
    loss_kernel<<<1, 1024>>>(tl, bias, out);
}

// round 7
// speedup vs baseline: 1.0010x; 1.0010x over previous
#include <cuda_runtime.h>
#include <math.h>

#define BSZ  32
#define SEQ  4096
#define ENC  512
#define TMAX 64

// Scratch: per-(b,t) logit-difference contributions. __device__ globals (no alloc).
__device__ float g_dl[BSZ * TMAX];
__device__ float g_dr[BSZ * TMAX];

// Kernel 1: gather + two weight-difference dot products per (b,t).
// 256 blocks x 256 threads; each warp owns one (b,t) row (2048 rows total).
__global__ void __launch_bounds__(256) proj_kernel(const float* __restrict__ enc,
                                                   const int*   __restrict__ ids,
                                                   const float* __restrict__ W) {
    __shared__ float wdl[ENC];
    __shared__ float wdr[ENC];
    const int tid = threadIdx.x;

    // Stage weight-difference vectors once per block.
    // W layout (2, 2*ENC) row-major: W0 = W[0..1024), W1 = W[1024..2048).
    for (int i = tid; i < ENC; i += 256) {
        wdl[i] = W[1024 + i]       - W[i];          // Wl1 - Wl0
        wdr[i] = W[1536 + i]       - W[512 + i];    // Wr1 - Wr0
    }
    __syncthreads();

    const int warp = tid >> 5;
    const int lane = tid & 31;
    const int row  = blockIdx.x * 8 + warp;         // 0..2047  == b*64 + t
    const int b    = row >> 6;
    const int id   = ids[row];

    const float4* __restrict__ src = (const float4*)(enc + ((size_t)b * SEQ + id) * ENC);
    const float4* __restrict__ l4  = (const float4*)wdl;
    const float4* __restrict__ r4  = (const float4*)wdr;

    float dl = 0.f, dr = 0.f;
#pragma unroll
    for (int i = 0; i < 4; i++) {
        const int c = lane + i * 32;                // 128 float4 per row
        const float4 x  = src[c];
        const float4 a  = l4[c];
        const float4 bb = r4[c];
        dl = fmaf(x.x, a.x,  fmaf(x.y, a.y,  fmaf(x.z, a.z,  fmaf(x.w, a.w,  dl))));
        dr = fmaf(x.x, bb.x, fmaf(x.y, bb.y, fmaf(x.z, bb.z, fmaf(x.w, bb.w, dr))));
    }
#pragma unroll
    for (int o = 16; o; o >>= 1) {
        dl += __shfl_xor_sync(0xffffffffu, dl, o);
        dr += __shfl_xor_sync(0xffffffffu, dr, o);
    }
    if (lane == 0) {
        g_dl[row] = dl;
        g_dr[row] = dr;
    }
}

// Kernel 2: pairwise masked CE + reduction. Single CTA (work is tiny).
__global__ void __launch_bounds__(1024) loss_kernel(const int*   __restrict__ tl,
                                                    const float* __restrict__ bias,
                                                    float*       __restrict__ out) {
    __shared__ float sdl[BSZ * TMAX];
    __shared__ float sdr[BSZ * TMAX];
    __shared__ int   slen[BSZ];
    __shared__ float swsum[32];
    __shared__ int   swcnt[32];

    const int tid = threadIdx.x;
    for (int i = tid; i < BSZ * TMAX; i += 1024) {
        sdl[i] = g_dl[i];
        sdr[i] = g_dr[i];
    }
    if (tid < BSZ) slen[tid] = tl[tid];
    __syncthreads();

    const float db = bias[1] - bias[0];

    float sum = 0.f;
    int   cnt = 0;
    // 32*64*64 = 131072 pairs, 128 per thread.
    for (int p = tid; p < BSZ * TMAX * TMAX; p += 1024) {
        const int b = p >> 12;
        const int j = (p >> 6) & 63;
        const int k = p & 63;
        if (k < j && j < slen[b]) {
            const float d = sdl[b * 64 + j] + sdr[b * 64 + k] + db;
            const float x = (k == j - 1) ? -d : d;       // label -> -logp1, else -logp0
            // numerically stable softplus(x) = max(x,0) + log1p(exp(-|x|))
            const float ce = fmaxf(x, 0.f) + log1pf(expf(-fabsf(x)));
            sum += ce;
            cnt += 1;
        }
    }

#pragma unroll
    for (int o = 16; o; o >>= 1) {
        sum += __shfl_xor_sync(0xffffffffu, sum, o);
        cnt += __shfl_xor_sync(0xffffffffu, cnt, o);
    }
    const int warp = tid >> 5;
    const int lane = tid & 31;
    if (lane == 0) { swsum[warp] = sum; swcnt[warp] = cnt; }
    __syncthreads();
    if (warp == 0) {
        sum = (lane < 32) ? swsum[lane] : 0.f;
        cnt = (lane < 32) ? swcnt[lane] : 0;
#pragma unroll
        for (int o = 16; o; o >>= 1) {
            sum += __shfl_xor_sync(0xffffffffu, sum, o);
            cnt += __shfl_xor_sync(0xffffffffu, cnt, o);
        }
        if (lane == 0) out[0] = sum / (float)max(cnt, 1);
    }
}

extern "C" void kernel_launch(void* const* d_in, const int* in_sizes, int n_in,
                              void* d_out, int out_size) {
    // metadata order: encoder_output, his_turn_end_ids, turn_lengths, W, b
    const float* enc  = (const float*)d_in[0];
    const int*   ids  = (const int*)  d_in[1];
    const int*   tl   = (const int*)  d_in[2];
    const float* W    = (const float*)d_in[3];
    const float* bias = (const float*)d_in[4];
    float*       out  = (float*)d_out;

    proj_kernel<<<256, 256>>>(enc, ids, W);
    loss_kernel<<<1, 1024>>>(tl, bias, out);
}